// round 1
// baseline (speedup 1.0000x reference)
#include <cuda_runtime.h>

#define BATCH   16384
#define IN_DIM  4096
#define OUT_DIM 64
#define BM      128
#define BKX     16              // x columns per chunk
#define BK      (BKX * 3)       // 48 feature rows per chunk
#define THREADS 256
#define NCHUNK  (IN_DIM / BKX)  // 256

// Combined weights: row r = i*3+f, col j.  w0 = c[...,0]*ws, w1 = c[...,1]*ws, wb.
__device__ float g_w[IN_DIM * 3 * OUT_DIM];

__global__ void prep_weights_kernel(const float* __restrict__ c,
                                    const float* __restrict__ ws,
                                    const float* __restrict__ wb) {
    int idx = blockIdx.x * blockDim.x + threadIdx.x;
    if (idx >= IN_DIM * OUT_DIM) return;
    int i = idx >> 6;
    int j = idx & 63;
    float w = ws[idx];
    g_w[(i * 3 + 0) * OUT_DIM + j] = c[idx * 2 + 0] * w;
    g_w[(i * 3 + 1) * OUT_DIM + j] = c[idx * 2 + 1] * w;
    g_w[(i * 3 + 2) * OUT_DIM + j] = wb[idx];
}

// Cubic B-spline basis on knots [-1,-0.5,0,0.5,1,(1)] via truncated powers,
// plus silu.  Verified against the Cox-de Boor reference piecewise polys.
__device__ __forceinline__ void kan_features(float xv, float& b0, float& b1, float& si) {
    float xc = fminf(fmaxf(xv, -1.0f), 1.0f);
    float y1 = xc + 1.0f;                  // always >= 0 after clamp
    float y2 = fmaxf(xc + 0.5f, 0.0f);
    float y3 = fmaxf(xc, 0.0f);
    float y4 = fmaxf(xc - 0.5f, 0.0f);
    float c1 = y1 * y1 * y1;
    float c2 = y2 * y2 * y2;
    float c3 = y3 * y3 * y3;
    float c4 = y4 * y4 * y4;
    const float k43  = 1.3333333333333333f;   // 4/3
    const float k163 = 5.3333333333333333f;   // 16/3
    b0 = fmaf(k43, c1, fmaf(-k163, c2, fmaf(8.0f, c3, -k163 * c4)));
    b1 = fmaf(k43, c2, fmaf(-6.0f, c3, 12.0f * c4));
    si = xv * __fdividef(1.0f, 1.0f + __expf(-xv));
}

__global__ __launch_bounds__(THREADS, 1)
void kan_main_kernel(const float* __restrict__ x, float* __restrict__ out) {
    __shared__ float As[BK][BM];         // 24 KB : features  [feat_row][m]
    __shared__ float Ws[BK][OUT_DIM];    // 12 KB : weights   [feat_row][j]

    const int t    = threadIdx.x;
    const int m    = t >> 1;             // 0..127 : batch row within tile (loader role)
    const int half = t & 1;              // which 8 of the 16 x-columns
    const long xbase = (long)(blockIdx.x * BM + m) * IN_DIM + half * 8;

    const int ty = t >> 4;               // 0..15 : row group (8 rows)
    const int tx = t & 15;               // 0..15 : col group (4 cols)

    float acc[8][4];
#pragma unroll
    for (int r = 0; r < 8; r++)
#pragma unroll
        for (int q = 0; q < 4; q++) acc[r][q] = 0.0f;

    float fr[24];   // staged features (8 x-values * 3)
    float wr[12];   // staged weights  (3 float4)

    // ---- preload chunk 0 into registers ----
    {
        float4 v0 = *(const float4*)(x + xbase + 0);
        float4 v1 = *(const float4*)(x + xbase + 4);
        float vx[8] = {v0.x, v0.y, v0.z, v0.w, v1.x, v1.y, v1.z, v1.w};
#pragma unroll
        for (int u = 0; u < 8; u++)
            kan_features(vx[u], fr[u * 3 + 0], fr[u * 3 + 1], fr[u * 3 + 2]);
        const float4* wsrc = (const float4*)g_w;
#pragma unroll
        for (int s = 0; s < 3; s++)
            *(float4*)&wr[s * 4] = wsrc[s * THREADS + t];
    }

    for (int ch = 0; ch < NCHUNK; ch++) {
        // ---- commit staged registers to smem ----
#pragma unroll
        for (int u = 0; u < 8; u++) {
            int kl = half * 8 + u;
            As[kl * 3 + 0][m] = fr[u * 3 + 0];
            As[kl * 3 + 1][m] = fr[u * 3 + 1];
            As[kl * 3 + 2][m] = fr[u * 3 + 2];
        }
#pragma unroll
        for (int s = 0; s < 3; s++)
            ((float4*)&Ws[0][0])[s * THREADS + t] = *(const float4*)&wr[s * 4];
        __syncthreads();

        // ---- issue global loads for next chunk (latency hides under FMA) ----
        float vx[8];
        const bool has_next = (ch + 1 < NCHUNK);
        if (has_next) {
            long nb = xbase + (long)(ch + 1) * BKX;
            float4 v0 = *(const float4*)(x + nb + 0);
            float4 v1 = *(const float4*)(x + nb + 4);
            vx[0] = v0.x; vx[1] = v0.y; vx[2] = v0.z; vx[3] = v0.w;
            vx[4] = v1.x; vx[5] = v1.y; vx[6] = v1.z; vx[7] = v1.w;
            const float4* wsrc = (const float4*)(g_w + (long)(ch + 1) * BK * OUT_DIM);
#pragma unroll
            for (int s = 0; s < 3; s++)
                *(float4*)&wr[s * 4] = wsrc[s * THREADS + t];
        }

        // ---- FMA over the chunk ----
#pragma unroll 8
        for (int kk = 0; kk < BK; kk++) {
            float4 a01 = *(const float4*)&As[kk][ty * 8 + 0];
            float4 a23 = *(const float4*)&As[kk][ty * 8 + 4];
            float4 b   = *(const float4*)&Ws[kk][tx * 4];
            float av[8] = {a01.x, a01.y, a01.z, a01.w, a23.x, a23.y, a23.z, a23.w};
            float bv[4] = {b.x, b.y, b.z, b.w};
#pragma unroll
            for (int r = 0; r < 8; r++)
#pragma unroll
                for (int q = 0; q < 4; q++)
                    acc[r][q] = fmaf(av[r], bv[q], acc[r][q]);
        }

        // ---- compute features for next chunk from staged x ----
        if (has_next) {
#pragma unroll
            for (int u = 0; u < 8; u++)
                kan_features(vx[u], fr[u * 3 + 0], fr[u * 3 + 1], fr[u * 3 + 2]);
        }
        __syncthreads();
    }

    // ---- writeout ----
#pragma unroll
    for (int r = 0; r < 8; r++) {
        long row = (long)blockIdx.x * BM + ty * 8 + r;
        float4 v = make_float4(acc[r][0], acc[r][1], acc[r][2], acc[r][3]);
        *(float4*)(out + row * OUT_DIM + tx * 4) = v;
    }
}

extern "C" void kernel_launch(void* const* d_in, const int* in_sizes, int n_in,
                              void* d_out, int out_size) {
    const float* x  = (const float*)d_in[0];
    const float* c  = (const float*)d_in[1];
    const float* ws = (const float*)d_in[2];
    const float* wb = (const float*)d_in[3];
    float* out = (float*)d_out;

    prep_weights_kernel<<<(IN_DIM * OUT_DIM + 255) / 256, 256>>>(c, ws, wb);
    kan_main_kernel<<<BATCH / BM, THREADS>>>(x, out);
}

// round 3
// speedup vs baseline: 2.2743x; 2.2743x over previous
#include <cuda_runtime.h>
#include <cstdint>

#define BATCH   16384
#define IN_DIM  4096
#define OUT_DIM 64
#define BM      128
#define XCH     16                 // x-cols per chunk
#define KCH     48                 // feature rows per chunk (3 per x-col)
#define NCH     (IN_DIM / XCH)     // 256 chunks
#define NS      6                  // k-steps (of 8) per chunk
#define THREADS 256

#define A_STRIDE 136               // pad: 136 % 32 == 8 -> conflict-free frag reads
#define A_BUF_FL (KCH * A_STRIDE)  // 6528 floats
#define B_BUF_FL (KCH * OUT_DIM)   // 3072 floats
#define SMEM_FL  (2 * A_BUF_FL + 2 * B_BUF_FL)   // 19200 floats = 76800 B

// Weights pre-arranged in mma-fragment order, chunk-major:
// [q][s][nt][lane][reg] ; k_local = s*8 + reg*4 + (lane&3), n = nt*8 + (lane>>2)
__device__ float g_w[NCH * B_BUF_FL];

__device__ __forceinline__ float tf32r(float v) {
    float o;
    asm("cvt.rna.tf32.f32 %0, %1;" : "=f"(o) : "f"(v));
    return o;
}

// Verified cubic B-spline basis (knots [-1,-.5,0,.5,1,(1)]) + silu, tf32-rounded.
__device__ __forceinline__ void kan_features(float xv, float& b0, float& b1, float& si) {
    float xc = fminf(fmaxf(xv, -1.0f), 1.0f);
    float y1 = xc + 1.0f;
    float y2 = fmaxf(xc + 0.5f, 0.0f);
    float y3 = fmaxf(xc, 0.0f);
    float y4 = fmaxf(xc - 0.5f, 0.0f);
    float c1 = y1 * y1 * y1;
    float c2 = y2 * y2 * y2;
    float c3 = y3 * y3 * y3;
    float c4 = y4 * y4 * y4;
    const float k43  = 1.3333333333333333f;
    const float k163 = 5.3333333333333333f;
    b0 = tf32r(fmaf(k43, c1, fmaf(-k163, c2, fmaf(8.0f, c3, -k163 * c4))));
    b1 = tf32r(fmaf(k43, c2, fmaf(-6.0f, c3, 12.0f * c4)));
    si = tf32r(xv * __fdividef(1.0f, 1.0f + __expf(-xv)));
}

// ---- weight prep: fragment-ordered tf32 B image ----
__global__ void prep_weights_kernel(const float* __restrict__ c,
                                    const float* __restrict__ ws,
                                    const float* __restrict__ wb) {
    int idx = blockIdx.x * blockDim.x + threadIdx.x;   // NCH*3072
    int q    = idx / B_BUF_FL;
    int rem  = idx - q * B_BUF_FL;
    int s    = rem >> 9;              // /512
    int rem2 = rem & 511;
    int nt   = rem2 >> 6;
    int l2   = rem2 & 63;
    int lane = l2 >> 1;
    int reg  = l2 & 1;
    int t = lane & 3, g = lane >> 2;
    int k_local = s * 8 + reg * 4 + t;
    int n  = nt * 8 + g;
    int li = k_local / 3;
    int f  = k_local - 3 * li;
    int i  = q * XCH + li;
    int ij = i * OUT_DIM + n;
    float v;
    if (f == 0)      v = c[ij * 2 + 0] * ws[ij];
    else if (f == 1) v = c[ij * 2 + 1] * ws[ij];
    else             v = wb[ij];
    g_w[idx] = tf32r(v);
}

__device__ __forceinline__ void mma_tf32(float* cc, uint32_t a0, uint32_t a1,
                                         uint32_t a2, uint32_t a3,
                                         uint32_t b0, uint32_t b1) {
    asm volatile("mma.sync.aligned.m16n8k8.row.col.f32.tf32.tf32.f32 "
                 "{%0,%1,%2,%3}, {%4,%5,%6,%7}, {%8,%9}, {%0,%1,%2,%3};"
                 : "+f"(cc[0]), "+f"(cc[1]), "+f"(cc[2]), "+f"(cc[3])
                 : "r"(a0), "r"(a1), "r"(a2), "r"(a3), "r"(b0), "r"(b1));
}

__device__ __forceinline__ void cp_async16(uint32_t dst, const void* src) {
    asm volatile("cp.async.cg.shared.global [%0], [%1], 16;"
                 :: "r"(dst), "l"(__cvta_generic_to_global(src)) : "memory");
}

__device__ __forceinline__ uint32_t smem_u32(const void* p) {
    uint32_t a;
    asm("{ .reg .u64 t; cvta.to.shared.u64 t, %1; cvt.u32.u64 %0, t; }" : "=r"(a) : "l"(p));
    return a;
}

__global__ __launch_bounds__(THREADS, 1)
void kan_main_kernel(const float* __restrict__ x, float* __restrict__ out) {
    extern __shared__ float sm[];
    float* As = sm;                       // [2][KCH][A_STRIDE]
    float* Bs = sm + 2 * A_BUF_FL;        // [2][NS][8][32][2]

    const int tid  = threadIdx.x;
    const int lane = tid & 31;
    const int wid  = tid >> 5;
    const int wr   = wid & 3;             // row group: 32 rows
    const int wc   = wid >> 2;            // col group: 32 cols
    const int g    = lane >> 2;
    const int t    = lane & 3;

    // feature-writer role
    const int frow = tid >> 1;            // 0..127
    const int h    = tid & 1;             // which 8 of 16 x-cols
    const float* xrow = x + (size_t)(blockIdx.x * BM + frow) * IN_DIM + h * 8;

    float cacc[2][4][4];
#pragma unroll
    for (int mt = 0; mt < 2; mt++)
#pragma unroll
        for (int q = 0; q < 4; q++)
#pragma unroll
            for (int r = 0; r < 4; r++) cacc[mt][q][r] = 0.0f;

    // ---- preload chunk 0: B via cp.async, x into regs ----
    {
        const float* src = g_w + tid * 4;
        uint32_t dst = smem_u32(Bs) + tid * 16;
#pragma unroll
        for (int i = 0; i < 3; i++)
            cp_async16(dst + i * THREADS * 16, src + i * THREADS * 4);
        asm volatile("cp.async.commit_group;" ::: "memory");
    }
    float4 xc0 = *(const float4*)(xrow + 0);
    float4 xc1 = *(const float4*)(xrow + 4);

    for (int ch = 0; ch < NCH; ch++) {
        const int b = ch & 1;

        // ---- features for this chunk -> As[b] ----
        {
            float* Ab = As + b * A_BUF_FL;
            float xs[8] = {xc0.x, xc0.y, xc0.z, xc0.w, xc1.x, xc1.y, xc1.z, xc1.w};
#pragma unroll
            for (int u = 0; u < 8; u++) {
                float f0, f1, f2;
                kan_features(xs[u], f0, f1, f2);
                int k = 3 * (h * 8 + u);
                Ab[(k + 0) * A_STRIDE + frow] = f0;
                Ab[(k + 1) * A_STRIDE + frow] = f1;
                Ab[(k + 2) * A_STRIDE + frow] = f2;
            }
        }

        const bool has_next = (ch + 1 < NCH);
        if (has_next) {
            // issue B copy for next chunk
            const float* src = g_w + (size_t)(ch + 1) * B_BUF_FL + tid * 4;
            uint32_t dst = smem_u32(Bs) + (b ^ 1) * B_BUF_FL * 4 + tid * 16;
#pragma unroll
            for (int i = 0; i < 3; i++)
                cp_async16(dst + i * THREADS * 16, src + i * THREADS * 4);
            asm volatile("cp.async.commit_group;" ::: "memory");
            // prefetch next x
            const float* nx = xrow + (ch + 1) * XCH;
            xc0 = *(const float4*)(nx + 0);
            xc1 = *(const float4*)(nx + 4);
        }

        if (has_next) asm volatile("cp.async.wait_group 1;" ::: "memory");
        else          asm volatile("cp.async.wait_group 0;" ::: "memory");
        __syncthreads();   // features + B[b] visible to all

        // ---- MMA over 6 k-steps ----
        {
            const float* Ab = As + b * A_BUF_FL + wr * 32;
            const float* Bb = Bs + b * B_BUF_FL + (wc * 4) * 64 + lane * 2;
#pragma unroll
            for (int s = 0; s < NS; s++) {
                uint32_t breg[4][2];
#pragma unroll
                for (int q = 0; q < 4; q++) {
                    float2 bv = *(const float2*)(Bb + (s * 8 + q) * 64);
                    breg[q][0] = __float_as_uint(bv.x);
                    breg[q][1] = __float_as_uint(bv.y);
                }
                const float* Ak0 = Ab + (s * 8 + t) * A_STRIDE + g;
                const float* Ak4 = Ak0 + 4 * A_STRIDE;
#pragma unroll
                for (int mt = 0; mt < 2; mt++) {
                    uint32_t a0 = __float_as_uint(Ak0[mt * 16 + 0]);
                    uint32_t a1 = __float_as_uint(Ak0[mt * 16 + 8]);
                    uint32_t a2 = __float_as_uint(Ak4[mt * 16 + 0]);
                    uint32_t a3 = __float_as_uint(Ak4[mt * 16 + 8]);
#pragma unroll
                    for (int q = 0; q < 4; q++)
                        mma_tf32(cacc[mt][q], a0, a1, a2, a3, breg[q][0], breg[q][1]);
                }
            }
        }
        __syncthreads();   // all reads of As[b]/Bs[b] done before overwrite
    }

    // ---- epilogue ----
    const int row0 = blockIdx.x * BM + wr * 32 + g;
    const int col0 = wc * 32 + t * 2;
#pragma unroll
    for (int mt = 0; mt < 2; mt++) {
#pragma unroll
        for (int q = 0; q < 4; q++) {
            int rA = row0 + mt * 16;
            int cA = col0 + q * 8;
            *(float2*)(out + (size_t)rA * OUT_DIM + cA) =
                make_float2(cacc[mt][q][0], cacc[mt][q][1]);
            *(float2*)(out + (size_t)(rA + 8) * OUT_DIM + cA) =
                make_float2(cacc[mt][q][2], cacc[mt][q][3]);
        }
    }
}

extern "C" void kernel_launch(void* const* d_in, const int* in_sizes, int n_in,
                              void* d_out, int out_size) {
    const float* x  = (const float*)d_in[0];
    const float* c  = (const float*)d_in[1];
    const float* ws = (const float*)d_in[2];
    const float* wb = (const float*)d_in[3];
    float* out = (float*)d_out;

    cudaFuncSetAttribute(kan_main_kernel, cudaFuncAttributeMaxDynamicSharedMemorySize,
                         SMEM_FL * 4);

    prep_weights_kernel<<<(NCH * B_BUF_FL) / 256, 256>>>(c, ws, wb);
    kan_main_kernel<<<BATCH / BM, THREADS, SMEM_FL * 4>>>(x, out);
}